// round 8
// baseline (speedup 1.0000x reference)
#include <cuda_runtime.h>
#include <cuda_bf16.h>
#include <cstdint>
#include <math.h>

// Problem constants
#define BATCH 4
#define SLEN 2048
#define DMODEL 1024
#define NHEADS 16
#define HDIM 64
#define QKV_LD 3072
#define MROWS (BATCH * SLEN)  // 8192

// Scratch (allocation-free rule: __device__ globals)
__device__ float g_qkv[(size_t)MROWS * QKV_LD];       // [8192, 3072] (tf32-rounded)
__device__ float g_ctx[(size_t)MROWS * DMODEL];       // [8192, 1024]
__device__ float g_wqkv_t[(size_t)QKV_LD * DMODEL];   // [3072, 1024]
__device__ float g_wout_t[(size_t)DMODEL * DMODEL];   // [1024, 1024]

// ---------------------------------------------------------------------------
// Helpers
// ---------------------------------------------------------------------------
__device__ __forceinline__ float tf32r(float x) {
    uint32_t u;
    asm("cvt.rna.tf32.f32 %0, %1;" : "=r"(u) : "f"(x));
    return __uint_as_float(u);
}

// m16n8k8 tf32 MMA: C[16x8] += A[16x8] * B[8x8]
__device__ __forceinline__ void mma8(float* c, const float* a, const float* b) {
    const uint32_t* A = reinterpret_cast<const uint32_t*>(a);
    const uint32_t* B = reinterpret_cast<const uint32_t*>(b);
    asm volatile(
        "mma.sync.aligned.m16n8k8.row.col.f32.tf32.tf32.f32 "
        "{%0,%1,%2,%3}, {%4,%5,%6,%7}, {%8,%9}, {%0,%1,%2,%3};"
        : "+f"(c[0]), "+f"(c[1]), "+f"(c[2]), "+f"(c[3])
        : "r"(A[0]), "r"(A[1]), "r"(A[2]), "r"(A[3]), "r"(B[0]), "r"(B[1]));
}

// Fast exp on the FMA pipe. x <= ~1, result >= 0.
__device__ __forceinline__ float fexp(float x) {
    float t = fmaxf(x * 1.4426950408889634f, -120.0f);
    float r = t + 12582912.0f;
    int   i = __float_as_int(r) - 0x4B400000;
    float f = t - (r - 12582912.0f);
    float p = 0.0013333558f;
    p = fmaf(p, f, 0.0096181291f);
    p = fmaf(p, f, 0.0555041087f);
    p = fmaf(p, f, 0.2402265069f);
    p = fmaf(p, f, 0.6931471806f);
    p = fmaf(p, f, 1.0f);
    return __int_as_float(__float_as_int(p) + (i << 23));
}

#define CPA_COMMIT() asm volatile("cp.async.commit_group;" ::: "memory")

// ---------------------------------------------------------------------------
// tf32 mma GEMM: C[M,N] = A[M,K] @ Bt[N,K]^T (both K-major).
// CTA tile 128x128, BK=32, 8 warps in 2x4, warp tile 64x32.
// round_out: store tf32-rounded result (for qkv scratch feeding attention mma)
// ---------------------------------------------------------------------------
#define GSTR 40
__global__ __launch_bounds__(256) void mma_gemm_kernel(
    const float* __restrict__ A, const float* __restrict__ Bt,
    float* __restrict__ C, int M, int N, int K, int round_out)
{
    __shared__ float As[128 * GSTR];
    __shared__ float Bs[128 * GSTR];

    const int tid = threadIdx.x;
    const int lane = tid & 31, wid = tid >> 5;
    const int g = lane >> 2, cq = lane & 3;
    const int wm = (wid >> 2) * 64, wn = (wid & 3) * 32;

    const float* Ablk = A + (size_t)blockIdx.y * 128 * K;
    const float* Bblk = Bt + (size_t)blockIdx.x * 128 * K;

    float acc[4][4][4] = {};

    for (int k0 = 0; k0 < K; k0 += 32) {
        #pragma unroll
        for (int i = 0; i < 4; i++) {
            int idx = tid + i * 256;
            int row = idx >> 3;
            int c4 = (idx & 7) << 2;
            float4 av = *(const float4*)&Ablk[(size_t)row * K + k0 + c4];
            float4 bv = *(const float4*)&Bblk[(size_t)row * K + k0 + c4];
            float* pa = &As[row * GSTR + c4];
            pa[0] = tf32r(av.x); pa[1] = tf32r(av.y);
            pa[2] = tf32r(av.z); pa[3] = tf32r(av.w);
            float* pb = &Bs[row * GSTR + c4];
            pb[0] = tf32r(bv.x); pb[1] = tf32r(bv.y);
            pb[2] = tf32r(bv.z); pb[3] = tf32r(bv.w);
        }
        __syncthreads();

        #pragma unroll
        for (int ks = 0; ks < 4; ks++) {
            float a[4][4], b[4][2];
            #pragma unroll
            for (int mi = 0; mi < 4; mi++) {
                int r = wm + mi * 16 + g;
                a[mi][0] = As[r * GSTR + ks * 8 + cq];
                a[mi][1] = As[(r + 8) * GSTR + ks * 8 + cq];
                a[mi][2] = As[r * GSTR + ks * 8 + cq + 4];
                a[mi][3] = As[(r + 8) * GSTR + ks * 8 + cq + 4];
            }
            #pragma unroll
            for (int nf = 0; nf < 4; nf++) {
                int n = wn + nf * 8 + g;
                b[nf][0] = Bs[n * GSTR + ks * 8 + cq];
                b[nf][1] = Bs[n * GSTR + ks * 8 + cq + 4];
            }
            #pragma unroll
            for (int mi = 0; mi < 4; mi++)
                #pragma unroll
                for (int nf = 0; nf < 4; nf++)
                    mma8(acc[mi][nf], a[mi], b[nf]);
        }
        __syncthreads();
    }

    #pragma unroll
    for (int mi = 0; mi < 4; mi++) {
        int row = blockIdx.y * 128 + wm + mi * 16 + g;
        #pragma unroll
        for (int nf = 0; nf < 4; nf++) {
            int col = blockIdx.x * 128 + wn + nf * 8 + 2 * cq;
            float4 vv = make_float4(acc[mi][nf][0], acc[mi][nf][1],
                                    acc[mi][nf][2], acc[mi][nf][3]);
            if (round_out) {
                vv.x = tf32r(vv.x); vv.y = tf32r(vv.y);
                vv.z = tf32r(vv.z); vv.w = tf32r(vv.w);
            }
            *(float2*)&C[(size_t)row * N + col] = make_float2(vv.x, vv.y);
            *(float2*)&C[(size_t)(row + 8) * N + col] = make_float2(vv.z, vv.w);
        }
    }
}

// ---------------------------------------------------------------------------
// Tiled transpose: out[c][r] = in[r][c], in is [R, C]
// ---------------------------------------------------------------------------
__global__ __launch_bounds__(256) void transpose_kernel(
    const float* __restrict__ in, float* __restrict__ out, int R, int C)
{
    __shared__ float t[32][33];
    int bx = blockIdx.x * 32, by = blockIdx.y * 32;
    int x = bx + threadIdx.x;
    #pragma unroll
    for (int i = 0; i < 32; i += 8) {
        int y = by + threadIdx.y + i;
        t[threadIdx.y + i][threadIdx.x] = in[(size_t)y * C + x];
    }
    __syncthreads();
    int xo = by + threadIdx.x;
    #pragma unroll
    for (int i = 0; i < 32; i += 8) {
        int yo = bx + threadIdx.y + i;
        out[(size_t)yo * R + xo] = t[threadIdx.x][threadIdx.y + i];
    }
}

// ---------------------------------------------------------------------------
// Flash attention v3: CTA = (b, h, 128-query tile), 4 warps x 32 q-rows.
// Q fragments register-resident; K/V double-buffered via cp.async.
// Dynamic smem arena (floats):
//   K0 @ 0      (32x68 = 2176)     K1 @ 2176
//   V0 @ 4352   (32x72 = 2304)     V1 @ 6656
//   P  @ 8960   (per warp 32x36 = 1152, 4 warps = 4608)
//   total 13568 floats = 54272 B.  Q staging [128x68=8704] aliases offset 0.
// ---------------------------------------------------------------------------
#define KSTR 68
#define VSTR 72
#define PSTR 36
#define SM_K0 0
#define SM_K1 2176
#define SM_V0 4352
#define SM_V1 6656
#define SM_P  8960
#define ATTN_SMEM_BYTES (13568 * 4)

__device__ __forceinline__ void issue_kv(uint32_t smbase, uint32_t kfoff, uint32_t vfoff,
                                         const float* kb, const float* vb, int kt, int tid)
{
    #pragma unroll
    for (int j = 0; j < 4; j++) {
        int idx = tid + j * 128;
        int row = idx >> 4;
        int c4 = (idx & 15) << 2;
        const float* ksrc = kb + (size_t)(kt + row) * QKV_LD + c4;
        uint32_t kdst = smbase + (kfoff + row * KSTR + c4) * 4;
        asm volatile("cp.async.cg.shared.global [%0], [%1], 16;" :: "r"(kdst), "l"(ksrc));
        const float* vsrc = vb + (size_t)(kt + row) * QKV_LD + c4;
        uint32_t vdst = smbase + (vfoff + row * VSTR + c4) * 4;
        asm volatile("cp.async.cg.shared.global [%0], [%1], 16;" :: "r"(vdst), "l"(vsrc));
    }
}

__global__ void __launch_bounds__(128, 2) attn_mma_kernel(
    const float* __restrict__ qkv, float* __restrict__ ctx)
{
    extern __shared__ float sm[];
    const int qt = blockIdx.x, h = blockIdx.y, b = blockIdx.z;
    const int tid = threadIdx.x;
    const int lane = tid & 31, w = tid >> 5;
    const int g = lane >> 2, cq = lane & 3;

    const int q0 = qt * 128;
    const float* base = qkv + (size_t)b * SLEN * QKV_LD + h * HDIM;
    const float* kb = base + 1024;
    const float* vb = base + 2048;

    uint32_t smbase;
    asm("{ .reg .u64 t; cvta.to.shared.u64 t, %1; cvt.u32.u64 %0, t; }" : "=r"(smbase) : "l"(sm));

    // Phase 0: stage Q [128x64] (pre-rounded in g_qkv; scale by exact 0.125)
    for (int i = tid; i < 2048; i += 128) {
        int row = i >> 4;
        int c4 = (i & 15) << 2;
        float4 v = *(const float4*)&base[(size_t)(q0 + row) * QKV_LD + c4];
        v.x *= 0.125f; v.y *= 0.125f; v.z *= 0.125f; v.w *= 0.125f;
        *(float4*)&sm[row * KSTR + c4] = v;
    }
    __syncthreads();

    // Q fragments to registers: qreg[mt][ks][4], rows w*32+16mt+g(+8)
    float qreg[2][8][4];
    const int rbase = w * 32 + g;
    #pragma unroll
    for (int mt = 0; mt < 2; mt++) {
        #pragma unroll
        for (int ks = 0; ks < 8; ks++) {
            int r0 = (rbase + 16 * mt) * KSTR + ks * 8 + cq;
            int r8 = (rbase + 16 * mt + 8) * KSTR + ks * 8 + cq;
            qreg[mt][ks][0] = sm[r0];
            qreg[mt][ks][1] = sm[r8];
            qreg[mt][ks][2] = sm[r0 + 4];
            qreg[mt][ks][3] = sm[r8 + 4];
        }
    }
    __syncthreads();

    // Prologue: tile 0 into buffer 0
    issue_kv(smbase, SM_K0, SM_V0, kb, vb, 0, tid);
    CPA_COMMIT();

    float oacc[2][8][4] = {};
    float mrow[4] = {-1e30f, -1e30f, -1e30f, -1e30f};
    float lrow[4] = {0.0f, 0.0f, 0.0f, 0.0f};
    float* Pw = &sm[SM_P + w * (32 * PSTR)];

    for (int it = 0; it < SLEN / 32; it++) {
        const int cur = it & 1;
        if (it + 1 < SLEN / 32) {
            issue_kv(smbase, cur ? SM_K0 : SM_K1, cur ? SM_V0 : SM_V1,
                     kb, vb, (it + 1) * 32, tid);
            CPA_COMMIT();
            asm volatile("cp.async.wait_group 1;" ::: "memory");
        } else {
            asm volatile("cp.async.wait_group 0;" ::: "memory");
        }
        __syncthreads();

        const float* Kc = &sm[cur ? SM_K1 : SM_K0];
        const float* Vc = &sm[cur ? SM_V1 : SM_V0];

        // S = Q @ K^T : 32 rows x 32 keys per warp
        float s[2][4][4] = {};
        #pragma unroll
        for (int ks = 0; ks < 8; ks++) {
            #pragma unroll
            for (int nf = 0; nf < 4; nf++) {
                float bf[2];
                int kaddr = (nf * 8 + g) * KSTR + ks * 8 + cq;
                bf[0] = Kc[kaddr];
                bf[1] = Kc[kaddr + 4];
                mma8(s[0][nf], qreg[0][ks], bf);
                mma8(s[1][nf], qreg[1][ks], bf);
            }
        }

        // Online softmax. Row groups j = mt*2 + half: rows rbase+16mt+8*half
        float rmax[4] = {-1e30f, -1e30f, -1e30f, -1e30f};
        #pragma unroll
        for (int mt = 0; mt < 2; mt++)
            #pragma unroll
            for (int nf = 0; nf < 4; nf++) {
                rmax[2 * mt]     = fmaxf(rmax[2 * mt],     fmaxf(s[mt][nf][0], s[mt][nf][1]));
                rmax[2 * mt + 1] = fmaxf(rmax[2 * mt + 1], fmaxf(s[mt][nf][2], s[mt][nf][3]));
            }
        float corr[4], mn[4];
        #pragma unroll
        for (int j = 0; j < 4; j++) {
            rmax[j] = fmaxf(rmax[j], __shfl_xor_sync(0xffffffffu, rmax[j], 1));
            rmax[j] = fmaxf(rmax[j], __shfl_xor_sync(0xffffffffu, rmax[j], 2));
            mn[j] = fmaxf(mrow[j], rmax[j]);
            corr[j] = fexp(mrow[j] - mn[j]);
            mrow[j] = mn[j];
        }

        float sum[4] = {0.0f, 0.0f, 0.0f, 0.0f};
        #pragma unroll
        for (int mt = 0; mt < 2; mt++) {
            #pragma unroll
            for (int nf = 0; nf < 4; nf++) {
                float p0 = fexp(s[mt][nf][0] - mn[2 * mt]);
                float p1 = fexp(s[mt][nf][1] - mn[2 * mt]);
                float p2 = fexp(s[mt][nf][2] - mn[2 * mt + 1]);
                float p3 = fexp(s[mt][nf][3] - mn[2 * mt + 1]);
                sum[2 * mt] += p0 + p1;
                sum[2 * mt + 1] += p2 + p3;
                int pr0 = (16 * mt + g) * PSTR + nf * 8 + 2 * cq;
                int pr8 = (16 * mt + g + 8) * PSTR + nf * 8 + 2 * cq;
                *(float2*)&Pw[pr0] = make_float2(tf32r(p0), tf32r(p1));
                *(float2*)&Pw[pr8] = make_float2(tf32r(p2), tf32r(p3));
            }
        }
        #pragma unroll
        for (int j = 0; j < 4; j++) {
            sum[j] += __shfl_xor_sync(0xffffffffu, sum[j], 1);
            sum[j] += __shfl_xor_sync(0xffffffffu, sum[j], 2);
            lrow[j] = lrow[j] * corr[j] + sum[j];
        }
        #pragma unroll
        for (int mt = 0; mt < 2; mt++)
            #pragma unroll
            for (int nf = 0; nf < 8; nf++) {
                oacc[mt][nf][0] *= corr[2 * mt];
                oacc[mt][nf][1] *= corr[2 * mt];
                oacc[mt][nf][2] *= corr[2 * mt + 1];
                oacc[mt][nf][3] *= corr[2 * mt + 1];
            }
        __syncwarp();

        // O += P @ V : 32 rows x 64 dims per warp
        #pragma unroll
        for (int ks = 0; ks < 4; ks++) {
            float a[2][4];
            #pragma unroll
            for (int mt = 0; mt < 2; mt++) {
                int p0 = (16 * mt + g) * PSTR + ks * 8 + cq;
                int p8 = (16 * mt + g + 8) * PSTR + ks * 8 + cq;
                a[mt][0] = Pw[p0];
                a[mt][1] = Pw[p8];
                a[mt][2] = Pw[p0 + 4];
                a[mt][3] = Pw[p8 + 4];
            }
            #pragma unroll
            for (int nf = 0; nf < 8; nf++) {
                float bf[2];
                int va = (ks * 8 + cq) * VSTR + nf * 8 + g;
                bf[0] = Vc[va];
                bf[1] = Vc[va + 4 * VSTR];
                mma8(oacc[0][nf], a[0], bf);
                mma8(oacc[1][nf], a[1], bf);
            }
        }
        __syncthreads();
    }

    // Normalize and store
    float inv[4];
    #pragma unroll
    for (int j = 0; j < 4; j++) inv[j] = 1.0f / lrow[j];
    float* cb = ctx + (size_t)b * SLEN * DMODEL + h * HDIM;
    #pragma unroll
    for (int mt = 0; mt < 2; mt++) {
        int row0 = q0 + rbase + 16 * mt;
        #pragma unroll
        for (int nf = 0; nf < 8; nf++) {
            int col = nf * 8 + 2 * cq;
            float2 v0 = make_float2(oacc[mt][nf][0] * inv[2 * mt], oacc[mt][nf][1] * inv[2 * mt]);
            float2 v1 = make_float2(oacc[mt][nf][2] * inv[2 * mt + 1], oacc[mt][nf][3] * inv[2 * mt + 1]);
            *(float2*)&cb[(size_t)row0 * DMODEL + col] = v0;
            *(float2*)&cb[(size_t)(row0 + 8) * DMODEL + col] = v1;
        }
    }
}

// ---------------------------------------------------------------------------
extern "C" void kernel_launch(void* const* d_in, const int* in_sizes, int n_in,
                              void* d_out, int out_size)
{
    const float* hs   = (const float*)d_in[0];
    const float* wqkv = (const float*)d_in[1];
    const float* wout = (const float*)d_in[2];
    float* out = (float*)d_out;

    float *qkv, *ctx, *wqkv_t, *wout_t;
    cudaGetSymbolAddress((void**)&qkv, g_qkv);
    cudaGetSymbolAddress((void**)&ctx, g_ctx);
    cudaGetSymbolAddress((void**)&wqkv_t, g_wqkv_t);
    cudaGetSymbolAddress((void**)&wout_t, g_wout_t);

    cudaFuncSetAttribute(attn_mma_kernel,
                         cudaFuncAttributeMaxDynamicSharedMemorySize, ATTN_SMEM_BYTES);

    // 0) Transpose weights to [N, K] K-major
    {
        dim3 blk(32, 8);
        transpose_kernel<<<dim3(QKV_LD / 32, DMODEL / 32), blk>>>(wqkv, wqkv_t, DMODEL, QKV_LD);
        transpose_kernel<<<dim3(DMODEL / 32, DMODEL / 32), blk>>>(wout, wout_t, DMODEL, DMODEL);
    }

    // 1) QKV projection (mma tf32), tf32-rounded output for attention
    {
        dim3 grid(QKV_LD / 128, MROWS / 128);
        mma_gemm_kernel<<<grid, 256>>>(hs, wqkv_t, qkv, MROWS, QKV_LD, DMODEL, 1);
    }

    // 2) Attention (mma tf32, cp.async double-buffered)
    {
        dim3 grid(SLEN / 128, NHEADS, BATCH);
        attn_mma_kernel<<<grid, 128, ATTN_SMEM_BYTES>>>(qkv, ctx);
    }

    // 3) Output projection (mma tf32)
    {
        dim3 grid(DMODEL / 128, MROWS / 128);
        mma_gemm_kernel<<<grid, 256>>>(ctx, wout_t, out, MROWS, DMODEL, DMODEL, 0);
    }
}

// round 11
// speedup vs baseline: 1.4899x; 1.4899x over previous
#include <cuda_runtime.h>
#include <cuda_bf16.h>
#include <cstdint>
#include <math.h>

// Problem constants
#define BATCH 4
#define SLEN 2048
#define DMODEL 1024
#define NHEADS 16
#define HDIM 64
#define QKV_LD 3072
#define MROWS (BATCH * SLEN)  // 8192

// Scratch (allocation-free rule: __device__ globals)
__device__ float g_qkv[(size_t)MROWS * QKV_LD];       // [8192, 3072] (tf32-rounded)
__device__ float g_ctx[(size_t)MROWS * DMODEL];       // [8192, 1024]
__device__ float g_wqkv_t[(size_t)QKV_LD * DMODEL];   // [3072, 1024]
__device__ float g_wout_t[(size_t)DMODEL * DMODEL];   // [1024, 1024]

// ---------------------------------------------------------------------------
// Helpers
// ---------------------------------------------------------------------------
__device__ __forceinline__ float tf32r(float x) {
    uint32_t u;
    asm("cvt.rna.tf32.f32 %0, %1;" : "=r"(u) : "f"(x));
    return __uint_as_float(u);
}

// m16n8k8 tf32 MMA: C[16x8] += A[16x8] * B[8x8]
__device__ __forceinline__ void mma8(float* c, const float* a, const float* b) {
    const uint32_t* A = reinterpret_cast<const uint32_t*>(a);
    const uint32_t* B = reinterpret_cast<const uint32_t*>(b);
    asm volatile(
        "mma.sync.aligned.m16n8k8.row.col.f32.tf32.tf32.f32 "
        "{%0,%1,%2,%3}, {%4,%5,%6,%7}, {%8,%9}, {%0,%1,%2,%3};"
        : "+f"(c[0]), "+f"(c[1]), "+f"(c[2]), "+f"(c[3])
        : "r"(A[0]), "r"(A[1]), "r"(A[2]), "r"(A[3]), "r"(B[0]), "r"(B[1]));
}

// Fast exp on the FMA pipe. x <= ~1, result >= 0.
__device__ __forceinline__ float fexp(float x) {
    float t = fmaxf(x * 1.4426950408889634f, -120.0f);
    float r = t + 12582912.0f;
    int   i = __float_as_int(r) - 0x4B400000;
    float f = t - (r - 12582912.0f);
    float p = 0.0013333558f;
    p = fmaf(p, f, 0.0096181291f);
    p = fmaf(p, f, 0.0555041087f);
    p = fmaf(p, f, 0.2402265069f);
    p = fmaf(p, f, 0.6931471806f);
    p = fmaf(p, f, 1.0f);
    return __int_as_float(__float_as_int(p) + (i << 23));
}

#define CPA_COMMIT() asm volatile("cp.async.commit_group;" ::: "memory")

// ---------------------------------------------------------------------------
// tf32 mma GEMM: C[M,N] = A[M,K] @ Bt[N,K]^T (both K-major).
// CTA tile 128x128, BK=32, 8 warps in 2x4, warp tile 64x32.
// round_out: store tf32-rounded result (for qkv scratch feeding attention mma)
// ---------------------------------------------------------------------------
#define GSTR 40
__global__ __launch_bounds__(256) void mma_gemm_kernel(
    const float* __restrict__ A, const float* __restrict__ Bt,
    float* __restrict__ C, int M, int N, int K, int round_out)
{
    __shared__ float As[128 * GSTR];
    __shared__ float Bs[128 * GSTR];

    const int tid = threadIdx.x;
    const int lane = tid & 31, wid = tid >> 5;
    const int g = lane >> 2, cq = lane & 3;
    const int wm = (wid >> 2) * 64, wn = (wid & 3) * 32;

    const float* Ablk = A + (size_t)blockIdx.y * 128 * K;
    const float* Bblk = Bt + (size_t)blockIdx.x * 128 * K;

    float acc[4][4][4] = {};

    for (int k0 = 0; k0 < K; k0 += 32) {
        #pragma unroll
        for (int i = 0; i < 4; i++) {
            int idx = tid + i * 256;
            int row = idx >> 3;
            int c4 = (idx & 7) << 2;
            float4 av = *(const float4*)&Ablk[(size_t)row * K + k0 + c4];
            float4 bv = *(const float4*)&Bblk[(size_t)row * K + k0 + c4];
            float* pa = &As[row * GSTR + c4];
            pa[0] = tf32r(av.x); pa[1] = tf32r(av.y);
            pa[2] = tf32r(av.z); pa[3] = tf32r(av.w);
            float* pb = &Bs[row * GSTR + c4];
            pb[0] = tf32r(bv.x); pb[1] = tf32r(bv.y);
            pb[2] = tf32r(bv.z); pb[3] = tf32r(bv.w);
        }
        __syncthreads();

        #pragma unroll
        for (int ks = 0; ks < 4; ks++) {
            float a[4][4], b[4][2];
            #pragma unroll
            for (int mi = 0; mi < 4; mi++) {
                int r = wm + mi * 16 + g;
                a[mi][0] = As[r * GSTR + ks * 8 + cq];
                a[mi][1] = As[(r + 8) * GSTR + ks * 8 + cq];
                a[mi][2] = As[r * GSTR + ks * 8 + cq + 4];
                a[mi][3] = As[(r + 8) * GSTR + ks * 8 + cq + 4];
            }
            #pragma unroll
            for (int nf = 0; nf < 4; nf++) {
                int n = wn + nf * 8 + g;
                b[nf][0] = Bs[n * GSTR + ks * 8 + cq];
                b[nf][1] = Bs[n * GSTR + ks * 8 + cq + 4];
            }
            #pragma unroll
            for (int mi = 0; mi < 4; mi++)
                #pragma unroll
                for (int nf = 0; nf < 4; nf++)
                    mma8(acc[mi][nf], a[mi], b[nf]);
        }
        __syncthreads();
    }

    #pragma unroll
    for (int mi = 0; mi < 4; mi++) {
        int row = blockIdx.y * 128 + wm + mi * 16 + g;
        #pragma unroll
        for (int nf = 0; nf < 4; nf++) {
            int col = blockIdx.x * 128 + wn + nf * 8 + 2 * cq;
            float4 vv = make_float4(acc[mi][nf][0], acc[mi][nf][1],
                                    acc[mi][nf][2], acc[mi][nf][3]);
            if (round_out) {
                vv.x = tf32r(vv.x); vv.y = tf32r(vv.y);
                vv.z = tf32r(vv.z); vv.w = tf32r(vv.w);
            }
            *(float2*)&C[(size_t)row * N + col] = make_float2(vv.x, vv.y);
            *(float2*)&C[(size_t)(row + 8) * N + col] = make_float2(vv.z, vv.w);
        }
    }
}

// ---------------------------------------------------------------------------
// Tiled transpose: out[c][r] = in[r][c], in is [R, C]
// ---------------------------------------------------------------------------
__global__ __launch_bounds__(256) void transpose_kernel(
    const float* __restrict__ in, float* __restrict__ out, int R, int C)
{
    __shared__ float t[32][33];
    int bx = blockIdx.x * 32, by = blockIdx.y * 32;
    int x = bx + threadIdx.x;
    #pragma unroll
    for (int i = 0; i < 32; i += 8) {
        int y = by + threadIdx.y + i;
        t[threadIdx.y + i][threadIdx.x] = in[(size_t)y * C + x];
    }
    __syncthreads();
    int xo = by + threadIdx.x;
    #pragma unroll
    for (int i = 0; i < 32; i += 8) {
        int yo = bx + threadIdx.y + i;
        out[(size_t)yo * R + xo] = t[threadIdx.x][threadIdx.y + i];
    }
}

// ---------------------------------------------------------------------------
// Flash attention v4: CTA = (b, h, 64-query tile), 4 warps x 16 q-rows.
// Q fragments register-resident (32 regs); K/V double-buffered via cp.async.
// Dynamic smem arena (floats):
//   K0 @ 0      (32x68 = 2176)     K1 @ 2176
//   V0 @ 4352   (32x72 = 2304)     V1 @ 6656
//   P  @ 8960   (per warp 16x36 = 576, 4 warps = 2304)
//   total 11264 floats = 45056 B.  Q staging [64x68=4352] aliases offset 0.
// ---------------------------------------------------------------------------
#define KSTR 68
#define VSTR 72
#define PSTR 36
#define SM_K0 0
#define SM_K1 2176
#define SM_V0 4352
#define SM_V1 6656
#define SM_P  8960
#define ATTN_SMEM_BYTES (11264 * 4)

__device__ __forceinline__ void issue_kv(uint32_t smbase, uint32_t kfoff, uint32_t vfoff,
                                         const float* kb, const float* vb, int kt, int tid)
{
    #pragma unroll
    for (int j = 0; j < 4; j++) {
        int idx = tid + j * 128;
        int row = idx >> 4;
        int c4 = (idx & 15) << 2;
        const float* ksrc = kb + (size_t)(kt + row) * QKV_LD + c4;
        uint32_t kdst = smbase + (kfoff + row * KSTR + c4) * 4;
        asm volatile("cp.async.cg.shared.global [%0], [%1], 16;" :: "r"(kdst), "l"(ksrc));
        const float* vsrc = vb + (size_t)(kt + row) * QKV_LD + c4;
        uint32_t vdst = smbase + (vfoff + row * VSTR + c4) * 4;
        asm volatile("cp.async.cg.shared.global [%0], [%1], 16;" :: "r"(vdst), "l"(vsrc));
    }
}

__global__ void __launch_bounds__(128) attn_mma_kernel(
    const float* __restrict__ qkv, float* __restrict__ ctx)
{
    extern __shared__ float sm[];
    const int qt = blockIdx.x, h = blockIdx.y, b = blockIdx.z;
    const int tid = threadIdx.x;
    const int lane = tid & 31, w = tid >> 5;
    const int g = lane >> 2, cq = lane & 3;

    const int q0 = qt * 64;
    const float* base = qkv + (size_t)b * SLEN * QKV_LD + h * HDIM;
    const float* kb = base + 1024;
    const float* vb = base + 2048;

    uint32_t smbase;
    asm("{ .reg .u64 t; cvta.to.shared.u64 t, %1; cvt.u32.u64 %0, t; }" : "=r"(smbase) : "l"(sm));

    // Phase 0: stage Q [64x64] (pre-rounded in g_qkv; scale by exact 0.125)
    for (int i = tid; i < 1024; i += 128) {
        int row = i >> 4;
        int c4 = (i & 15) << 2;
        float4 v = *(const float4*)&base[(size_t)(q0 + row) * QKV_LD + c4];
        v.x *= 0.125f; v.y *= 0.125f; v.z *= 0.125f; v.w *= 0.125f;
        *(float4*)&sm[row * KSTR + c4] = v;
    }
    __syncthreads();

    // Q fragments to registers: rows w*16+g, w*16+g+8
    float qreg[8][4];
    const int rbase = w * 16 + g;
    #pragma unroll
    for (int ks = 0; ks < 8; ks++) {
        int r0 = rbase * KSTR + ks * 8 + cq;
        int r8 = (rbase + 8) * KSTR + ks * 8 + cq;
        qreg[ks][0] = sm[r0];
        qreg[ks][1] = sm[r8];
        qreg[ks][2] = sm[r0 + 4];
        qreg[ks][3] = sm[r8 + 4];
    }
    __syncthreads();

    // Prologue: tile 0 into buffer 0
    issue_kv(smbase, SM_K0, SM_V0, kb, vb, 0, tid);
    CPA_COMMIT();

    float oacc[8][4] = {};
    float mrow[2] = {-1e30f, -1e30f};
    float lrow[2] = {0.0f, 0.0f};
    float* Pw = &sm[SM_P + w * (16 * PSTR)];

    for (int it = 0; it < SLEN / 32; it++) {
        const int cur = it & 1;
        if (it + 1 < SLEN / 32) {
            issue_kv(smbase, cur ? SM_K0 : SM_K1, cur ? SM_V0 : SM_V1,
                     kb, vb, (it + 1) * 32, tid);
            CPA_COMMIT();
            asm volatile("cp.async.wait_group 1;" ::: "memory");
        } else {
            asm volatile("cp.async.wait_group 0;" ::: "memory");
        }
        __syncthreads();

        const float* Kc = &sm[cur ? SM_K1 : SM_K0];
        const float* Vc = &sm[cur ? SM_V1 : SM_V0];

        // S = Q @ K^T : 16 rows x 32 keys per warp
        float s[4][4] = {};
        #pragma unroll
        for (int ks = 0; ks < 8; ks++) {
            #pragma unroll
            for (int nf = 0; nf < 4; nf++) {
                float bf[2];
                int kaddr = (nf * 8 + g) * KSTR + ks * 8 + cq;
                bf[0] = Kc[kaddr];
                bf[1] = Kc[kaddr + 4];
                mma8(s[nf], qreg[ks], bf);
            }
        }

        // Online softmax. Row j=0: rbase (c0,c1); j=1: rbase+8 (c2,c3)
        float rmax0 = -1e30f, rmax8 = -1e30f;
        #pragma unroll
        for (int nf = 0; nf < 4; nf++) {
            rmax0 = fmaxf(rmax0, fmaxf(s[nf][0], s[nf][1]));
            rmax8 = fmaxf(rmax8, fmaxf(s[nf][2], s[nf][3]));
        }
        rmax0 = fmaxf(rmax0, __shfl_xor_sync(0xffffffffu, rmax0, 1));
        rmax0 = fmaxf(rmax0, __shfl_xor_sync(0xffffffffu, rmax0, 2));
        rmax8 = fmaxf(rmax8, __shfl_xor_sync(0xffffffffu, rmax8, 1));
        rmax8 = fmaxf(rmax8, __shfl_xor_sync(0xffffffffu, rmax8, 2));

        float mn0 = fmaxf(mrow[0], rmax0), mn8 = fmaxf(mrow[1], rmax8);
        float corr0 = fexp(mrow[0] - mn0), corr8 = fexp(mrow[1] - mn8);
        mrow[0] = mn0; mrow[1] = mn8;

        float sum0 = 0.0f, sum8 = 0.0f;
        #pragma unroll
        for (int nf = 0; nf < 4; nf++) {
            float p0 = fexp(s[nf][0] - mn0);
            float p1 = fexp(s[nf][1] - mn0);
            float p2 = fexp(s[nf][2] - mn8);
            float p3 = fexp(s[nf][3] - mn8);
            sum0 += p0 + p1;
            sum8 += p2 + p3;
            *(float2*)&Pw[g * PSTR + nf * 8 + 2 * cq] = make_float2(tf32r(p0), tf32r(p1));
            *(float2*)&Pw[(g + 8) * PSTR + nf * 8 + 2 * cq] = make_float2(tf32r(p2), tf32r(p3));
        }
        sum0 += __shfl_xor_sync(0xffffffffu, sum0, 1);
        sum0 += __shfl_xor_sync(0xffffffffu, sum0, 2);
        sum8 += __shfl_xor_sync(0xffffffffu, sum8, 1);
        sum8 += __shfl_xor_sync(0xffffffffu, sum8, 2);
        lrow[0] = lrow[0] * corr0 + sum0;
        lrow[1] = lrow[1] * corr8 + sum8;

        #pragma unroll
        for (int nf = 0; nf < 8; nf++) {
            oacc[nf][0] *= corr0; oacc[nf][1] *= corr0;
            oacc[nf][2] *= corr8; oacc[nf][3] *= corr8;
        }
        __syncwarp();

        // O += P @ V : 16 rows x 64 dims per warp
        #pragma unroll
        for (int ks = 0; ks < 4; ks++) {
            float a[4];
            int p0a = g * PSTR + ks * 8 + cq;
            int p8a = (g + 8) * PSTR + ks * 8 + cq;
            a[0] = Pw[p0a];
            a[1] = Pw[p8a];
            a[2] = Pw[p0a + 4];
            a[3] = Pw[p8a + 4];
            #pragma unroll
            for (int nf = 0; nf < 8; nf++) {
                float bf[2];
                int va = (ks * 8 + cq) * VSTR + nf * 8 + g;
                bf[0] = Vc[va];
                bf[1] = Vc[va + 4 * VSTR];
                mma8(oacc[nf], a, bf);
            }
        }
        __syncthreads();
    }

    // Normalize and store
    float inv0 = 1.0f / lrow[0], inv8 = 1.0f / lrow[1];
    float* cb = ctx + (size_t)b * SLEN * DMODEL + h * HDIM;
    int row0 = q0 + rbase;
    #pragma unroll
    for (int nf = 0; nf < 8; nf++) {
        int col = nf * 8 + 2 * cq;
        float2 v0 = make_float2(oacc[nf][0] * inv0, oacc[nf][1] * inv0);
        float2 v1 = make_float2(oacc[nf][2] * inv8, oacc[nf][3] * inv8);
        *(float2*)&cb[(size_t)row0 * DMODEL + col] = v0;
        *(float2*)&cb[(size_t)(row0 + 8) * DMODEL + col] = v1;
    }
}

// ---------------------------------------------------------------------------
extern "C" void kernel_launch(void* const* d_in, const int* in_sizes, int n_in,
                              void* d_out, int out_size)
{
    const float* hs   = (const float*)d_in[0];
    const float* wqkv = (const float*)d_in[1];
    const float* wout = (const float*)d_in[2];
    float* out = (float*)d_out;

    float *qkv, *ctx, *wqkv_t, *wout_t;
    cudaGetSymbolAddress((void**)&qkv, g_qkv);
    cudaGetSymbolAddress((void**)&ctx, g_ctx);
    cudaGetSymbolAddress((void**)&wqkv_t, g_wqkv_t);
    cudaGetSymbolAddress((void**)&wout_t, g_wout_t);

    cudaFuncSetAttribute(attn_mma_kernel,
                         cudaFuncAttributeMaxDynamicSharedMemorySize, ATTN_SMEM_BYTES);

    // 0) Transpose weights to [N, K] K-major
    {
        dim3 blk(32, 8);
        transpose_kernel<<<dim3(QKV_LD / 32, DMODEL / 32), blk>>>(wqkv, wqkv_t, DMODEL, QKV_LD);
        transpose_kernel<<<dim3(DMODEL / 32, DMODEL / 32), blk>>>(wout, wout_t, DMODEL, DMODEL);
    }

    // 1) QKV projection (mma tf32), tf32-rounded output for attention
    {
        dim3 grid(QKV_LD / 128, MROWS / 128);
        mma_gemm_kernel<<<grid, 256>>>(hs, wqkv_t, qkv, MROWS, QKV_LD, DMODEL, 1);
    }

    // 2) Attention (mma tf32, cp.async double-buffered, Q in registers)
    {
        dim3 grid(SLEN / 64, NHEADS, BATCH);
        attn_mma_kernel<<<grid, 128, ATTN_SMEM_BYTES>>>(qkv, ctx);
    }

    // 3) Output projection (mma tf32)
    {
        dim3 grid(DMODEL / 128, MROWS / 128);
        mma_gemm_kernel<<<grid, 256>>>(ctx, wout_t, out, MROWS, DMODEL, DMODEL, 0);
    }
}

// round 13
// speedup vs baseline: 1.5477x; 1.0388x over previous
#include <cuda_runtime.h>
#include <cuda_bf16.h>
#include <cstdint>
#include <math.h>

// Problem constants
#define BATCH 4
#define SLEN 2048
#define DMODEL 1024
#define NHEADS 16
#define HDIM 64
#define QKV_LD 3072
#define MROWS (BATCH * SLEN)  // 8192

// Scratch (allocation-free rule: __device__ globals)
// g_ctx doubles as: rounded-hs (phase 1) then attention output (phase 2+).
__device__ float g_qkv[(size_t)MROWS * QKV_LD];       // [8192, 3072] (tf32-rounded)
__device__ float g_ctx[(size_t)MROWS * DMODEL];       // [8192, 1024]
__device__ float g_wqkv_t[(size_t)QKV_LD * DMODEL];   // [3072, 1024] (rounded)
__device__ float g_wout_t[(size_t)DMODEL * DMODEL];   // [1024, 1024] (rounded)

// ---------------------------------------------------------------------------
// Helpers
// ---------------------------------------------------------------------------
__device__ __forceinline__ float tf32r(float x) {
    uint32_t u;
    asm("cvt.rna.tf32.f32 %0, %1;" : "=r"(u) : "f"(x));
    return __uint_as_float(u);
}

// m16n8k8 tf32 MMA: C[16x8] += A[16x8] * B[8x8]
__device__ __forceinline__ void mma8(float* c, const float* a, const float* b) {
    const uint32_t* A = reinterpret_cast<const uint32_t*>(a);
    const uint32_t* B = reinterpret_cast<const uint32_t*>(b);
    asm volatile(
        "mma.sync.aligned.m16n8k8.row.col.f32.tf32.tf32.f32 "
        "{%0,%1,%2,%3}, {%4,%5,%6,%7}, {%8,%9}, {%0,%1,%2,%3};"
        : "+f"(c[0]), "+f"(c[1]), "+f"(c[2]), "+f"(c[3])
        : "r"(A[0]), "r"(A[1]), "r"(A[2]), "r"(A[3]), "r"(B[0]), "r"(B[1]));
}

// Fast exp on the FMA pipe. x <= ~1, result >= 0.
__device__ __forceinline__ float fexp(float x) {
    float t = fmaxf(x * 1.4426950408889634f, -120.0f);
    float r = t + 12582912.0f;
    int   i = __float_as_int(r) - 0x4B400000;
    float f = t - (r - 12582912.0f);
    float p = 0.0013333558f;
    p = fmaf(p, f, 0.0096181291f);
    p = fmaf(p, f, 0.0555041087f);
    p = fmaf(p, f, 0.2402265069f);
    p = fmaf(p, f, 0.6931471806f);
    p = fmaf(p, f, 1.0f);
    return __int_as_float(__float_as_int(p) + (i << 23));
}

#define CPA_COMMIT() asm volatile("cp.async.commit_group;" ::: "memory")
#define CPA(dst, src) \
    asm volatile("cp.async.cg.shared.global [%0], [%1], 16;" :: "r"(dst), "l"(src))

// ---------------------------------------------------------------------------
// Elementwise tf32 round: out[i] = tf32r(in[i]) (float4 grid-stride)
// ---------------------------------------------------------------------------
__global__ __launch_bounds__(256) void round_kernel(
    const float* __restrict__ in, float* __restrict__ out, int n4)
{
    int i = blockIdx.x * blockDim.x + threadIdx.x;
    int stride = gridDim.x * blockDim.x;
    for (; i < n4; i += stride) {
        float4 v = *(const float4*)&in[(size_t)i * 4];
        v.x = tf32r(v.x); v.y = tf32r(v.y); v.z = tf32r(v.z); v.w = tf32r(v.w);
        *(float4*)&out[(size_t)i * 4] = v;
    }
}

// ---------------------------------------------------------------------------
// Tiled transpose + tf32 round: out[c][r] = tf32r(in[r][c]), in is [R, C]
// ---------------------------------------------------------------------------
__global__ __launch_bounds__(256) void transpose_kernel(
    const float* __restrict__ in, float* __restrict__ out, int R, int C)
{
    __shared__ float t[32][33];
    int bx = blockIdx.x * 32, by = blockIdx.y * 32;
    int x = bx + threadIdx.x;
    #pragma unroll
    for (int i = 0; i < 32; i += 8) {
        int y = by + threadIdx.y + i;
        t[threadIdx.y + i][threadIdx.x] = in[(size_t)y * C + x];
    }
    __syncthreads();
    int xo = by + threadIdx.x;
    #pragma unroll
    for (int i = 0; i < 32; i += 8) {
        int yo = bx + threadIdx.y + i;
        out[(size_t)yo * R + xo] = tf32r(t[threadIdx.x][threadIdx.y + i]);
    }
}

// ---------------------------------------------------------------------------
// tf32 mma GEMM v2: C[M,N] = A[M,K] @ Bt[N,K]^T, inputs PRE-ROUNDED to tf32.
// CTA tile 128x128, BK=32, cp.async double-buffered, 8 warps 2x4.
// Dynamic smem (floats): As0 @0, As1 @5120, Bs0 @10240, Bs1 @15360 (81920 B)
// ---------------------------------------------------------------------------
#define GSTR 40
#define GEMM_SMEM_BYTES (20480 * 4)

__global__ __launch_bounds__(256) void mma_gemm_kernel(
    const float* __restrict__ A, const float* __restrict__ Bt,
    float* __restrict__ C, int M, int N, int K, int round_out)
{
    extern __shared__ float sm[];
    const int tid = threadIdx.x;
    const int lane = tid & 31, wid = tid >> 5;
    const int g = lane >> 2, cq = lane & 3;
    const int wm = (wid >> 2) * 64, wn = (wid & 3) * 32;

    const float* Ablk = A + (size_t)blockIdx.y * 128 * K;
    const float* Bblk = Bt + (size_t)blockIdx.x * 128 * K;

    uint32_t smbase;
    asm("{ .reg .u64 t; cvta.to.shared.u64 t, %1; cvt.u32.u64 %0, t; }" : "=r"(smbase) : "l"(sm));

    // load map: 1024 float4 per matrix per chunk; 4 per thread each
    const int lrow = tid >> 1;                 // 0..127
    const int lc4 = (tid & 1) << 2;            // 0 or 4 -> cols 0..7 over 2 steps
    // simpler: idx-based
    auto issue_chunk = [&](int k0, int buf) {
        uint32_t aoff = buf ? 5120u : 0u;
        uint32_t boff = buf ? 15360u : 10240u;
        #pragma unroll
        for (int i = 0; i < 4; i++) {
            int idx = tid + i * 256;           // 0..1023
            int row = idx >> 3;                // 0..127
            int c4 = (idx & 7) << 2;           // 0..28
            const float* asrc = &Ablk[(size_t)row * K + k0 + c4];
            CPA(smbase + (aoff + row * GSTR + c4) * 4, asrc);
            const float* bsrc = &Bblk[(size_t)row * K + k0 + c4];
            CPA(smbase + (boff + row * GSTR + c4) * 4, bsrc);
        }
        CPA_COMMIT();
    };

    issue_chunk(0, 0);

    float acc[4][4][4] = {};
    const int nchunks = K >> 5;

    for (int it = 0; it < nchunks; it++) {
        const int cur = it & 1;
        if (it + 1 < nchunks) {
            issue_chunk((it + 1) << 5, cur ^ 1);
            asm volatile("cp.async.wait_group 1;" ::: "memory");
        } else {
            asm volatile("cp.async.wait_group 0;" ::: "memory");
        }
        __syncthreads();

        const float* As = &sm[cur ? 5120 : 0];
        const float* Bs = &sm[cur ? 15360 : 10240];

        #pragma unroll
        for (int ks = 0; ks < 4; ks++) {
            float a[4][4], b[4][2];
            #pragma unroll
            for (int mi = 0; mi < 4; mi++) {
                int r = wm + mi * 16 + g;
                a[mi][0] = As[r * GSTR + ks * 8 + cq];
                a[mi][1] = As[(r + 8) * GSTR + ks * 8 + cq];
                a[mi][2] = As[r * GSTR + ks * 8 + cq + 4];
                a[mi][3] = As[(r + 8) * GSTR + ks * 8 + cq + 4];
            }
            #pragma unroll
            for (int nf = 0; nf < 4; nf++) {
                int n = wn + nf * 8 + g;
                b[nf][0] = Bs[n * GSTR + ks * 8 + cq];
                b[nf][1] = Bs[n * GSTR + ks * 8 + cq + 4];
            }
            #pragma unroll
            for (int mi = 0; mi < 4; mi++)
                #pragma unroll
                for (int nf = 0; nf < 4; nf++)
                    mma8(acc[mi][nf], a[mi], b[nf]);
        }
        __syncthreads();
    }

    #pragma unroll
    for (int mi = 0; mi < 4; mi++) {
        int row = blockIdx.y * 128 + wm + mi * 16 + g;
        #pragma unroll
        for (int nf = 0; nf < 4; nf++) {
            int col = blockIdx.x * 128 + wn + nf * 8 + 2 * cq;
            float4 vv = make_float4(acc[mi][nf][0], acc[mi][nf][1],
                                    acc[mi][nf][2], acc[mi][nf][3]);
            if (round_out) {
                vv.x = tf32r(vv.x); vv.y = tf32r(vv.y);
                vv.z = tf32r(vv.z); vv.w = tf32r(vv.w);
            }
            *(float2*)&C[(size_t)row * N + col] = make_float2(vv.x, vv.y);
            *(float2*)&C[(size_t)(row + 8) * N + col] = make_float2(vv.z, vv.w);
        }
    }
}

// ---------------------------------------------------------------------------
// Flash attention v5: CTA = (b, h, 128-query tile), 8 warps x 16 q-rows.
// Q fragments register-resident; K/V double-buffered via cp.async.
// Dynamic smem arena (floats):
//   K0 @ 0      (32x68 = 2176)     K1 @ 2176
//   V0 @ 4352   (32x72 = 2304)     V1 @ 6656
//   P  @ 8960   (per warp 16x36 = 576, 8 warps = 4608)
//   total 13568 floats = 54272 B.  Q staging [128x68=8704] aliases offset 0.
// ---------------------------------------------------------------------------
#define KSTR 68
#define VSTR 72
#define PSTR 36
#define SM_K0 0
#define SM_K1 2176
#define SM_V0 4352
#define SM_V1 6656
#define SM_P  8960
#define ATTN_SMEM_BYTES (13568 * 4)

__device__ __forceinline__ void issue_kv(uint32_t smbase, uint32_t kfoff, uint32_t vfoff,
                                         const float* kb, const float* vb, int kt, int tid)
{
    #pragma unroll
    for (int j = 0; j < 2; j++) {
        int idx = tid + j * 256;               // 0..511
        int row = idx >> 4;
        int c4 = (idx & 15) << 2;
        const float* ksrc = kb + (size_t)(kt + row) * QKV_LD + c4;
        CPA(smbase + (kfoff + row * KSTR + c4) * 4, ksrc);
        const float* vsrc = vb + (size_t)(kt + row) * QKV_LD + c4;
        CPA(smbase + (vfoff + row * VSTR + c4) * 4, vsrc);
    }
    CPA_COMMIT();
}

__global__ void __launch_bounds__(256) attn_mma_kernel(
    const float* __restrict__ qkv, float* __restrict__ ctx)
{
    extern __shared__ float sm[];
    const int qt = blockIdx.x, h = blockIdx.y, b = blockIdx.z;
    const int tid = threadIdx.x;
    const int lane = tid & 31, w = tid >> 5;
    const int g = lane >> 2, cq = lane & 3;

    const int q0 = qt * 128;
    const float* base = qkv + (size_t)b * SLEN * QKV_LD + h * HDIM;
    const float* kb = base + 1024;
    const float* vb = base + 2048;

    uint32_t smbase;
    asm("{ .reg .u64 t; cvta.to.shared.u64 t, %1; cvt.u32.u64 %0, t; }" : "=r"(smbase) : "l"(sm));

    // Phase 0: stage Q [128x64] (pre-rounded; scale by exact 0.125)
    for (int i = tid; i < 2048; i += 256) {
        int row = i >> 4;
        int c4 = (i & 15) << 2;
        float4 v = *(const float4*)&base[(size_t)(q0 + row) * QKV_LD + c4];
        v.x *= 0.125f; v.y *= 0.125f; v.z *= 0.125f; v.w *= 0.125f;
        *(float4*)&sm[row * KSTR + c4] = v;
    }
    __syncthreads();

    // Q fragments to registers: rows w*16+g, w*16+g+8
    float qreg[8][4];
    const int rbase = w * 16 + g;
    #pragma unroll
    for (int ks = 0; ks < 8; ks++) {
        int r0 = rbase * KSTR + ks * 8 + cq;
        int r8 = (rbase + 8) * KSTR + ks * 8 + cq;
        qreg[ks][0] = sm[r0];
        qreg[ks][1] = sm[r8];
        qreg[ks][2] = sm[r0 + 4];
        qreg[ks][3] = sm[r8 + 4];
    }
    __syncthreads();

    // Prologue: tile 0 into buffer 0
    issue_kv(smbase, SM_K0, SM_V0, kb, vb, 0, tid);

    float oacc[8][4] = {};
    float mrow[2] = {-1e30f, -1e30f};
    float lrow[2] = {0.0f, 0.0f};
    float* Pw = &sm[SM_P + w * (16 * PSTR)];

    for (int it = 0; it < SLEN / 32; it++) {
        const int cur = it & 1;
        if (it + 1 < SLEN / 32) {
            issue_kv(smbase, cur ? SM_K0 : SM_K1, cur ? SM_V0 : SM_V1,
                     kb, vb, (it + 1) * 32, tid);
            asm volatile("cp.async.wait_group 1;" ::: "memory");
        } else {
            asm volatile("cp.async.wait_group 0;" ::: "memory");
        }
        __syncthreads();

        const float* Kc = &sm[cur ? SM_K1 : SM_K0];
        const float* Vc = &sm[cur ? SM_V1 : SM_V0];

        // S = Q @ K^T : 16 rows x 32 keys per warp
        float s[4][4] = {};
        #pragma unroll
        for (int ks = 0; ks < 8; ks++) {
            #pragma unroll
            for (int nf = 0; nf < 4; nf++) {
                float bf[2];
                int kaddr = (nf * 8 + g) * KSTR + ks * 8 + cq;
                bf[0] = Kc[kaddr];
                bf[1] = Kc[kaddr + 4];
                mma8(s[nf], qreg[ks], bf);
            }
        }

        // Online softmax
        float rmax0 = -1e30f, rmax8 = -1e30f;
        #pragma unroll
        for (int nf = 0; nf < 4; nf++) {
            rmax0 = fmaxf(rmax0, fmaxf(s[nf][0], s[nf][1]));
            rmax8 = fmaxf(rmax8, fmaxf(s[nf][2], s[nf][3]));
        }
        rmax0 = fmaxf(rmax0, __shfl_xor_sync(0xffffffffu, rmax0, 1));
        rmax0 = fmaxf(rmax0, __shfl_xor_sync(0xffffffffu, rmax0, 2));
        rmax8 = fmaxf(rmax8, __shfl_xor_sync(0xffffffffu, rmax8, 1));
        rmax8 = fmaxf(rmax8, __shfl_xor_sync(0xffffffffu, rmax8, 2));

        float mn0 = fmaxf(mrow[0], rmax0), mn8 = fmaxf(mrow[1], rmax8);
        float corr0 = fexp(mrow[0] - mn0), corr8 = fexp(mrow[1] - mn8);
        mrow[0] = mn0; mrow[1] = mn8;

        float sum0 = 0.0f, sum8 = 0.0f;
        #pragma unroll
        for (int nf = 0; nf < 4; nf++) {
            float p0 = fexp(s[nf][0] - mn0);
            float p1 = fexp(s[nf][1] - mn0);
            float p2 = fexp(s[nf][2] - mn8);
            float p3 = fexp(s[nf][3] - mn8);
            sum0 += p0 + p1;
            sum8 += p2 + p3;
            *(float2*)&Pw[g * PSTR + nf * 8 + 2 * cq] = make_float2(tf32r(p0), tf32r(p1));
            *(float2*)&Pw[(g + 8) * PSTR + nf * 8 + 2 * cq] = make_float2(tf32r(p2), tf32r(p3));
        }
        sum0 += __shfl_xor_sync(0xffffffffu, sum0, 1);
        sum0 += __shfl_xor_sync(0xffffffffu, sum0, 2);
        sum8 += __shfl_xor_sync(0xffffffffu, sum8, 1);
        sum8 += __shfl_xor_sync(0xffffffffu, sum8, 2);
        lrow[0] = lrow[0] * corr0 + sum0;
        lrow[1] = lrow[1] * corr8 + sum8;

        #pragma unroll
        for (int nf = 0; nf < 8; nf++) {
            oacc[nf][0] *= corr0; oacc[nf][1] *= corr0;
            oacc[nf][2] *= corr8; oacc[nf][3] *= corr8;
        }
        __syncwarp();

        // O += P @ V : 16 rows x 64 dims per warp
        #pragma unroll
        for (int ks = 0; ks < 4; ks++) {
            float a[4];
            int p0a = g * PSTR + ks * 8 + cq;
            int p8a = (g + 8) * PSTR + ks * 8 + cq;
            a[0] = Pw[p0a];
            a[1] = Pw[p8a];
            a[2] = Pw[p0a + 4];
            a[3] = Pw[p8a + 4];
            #pragma unroll
            for (int nf = 0; nf < 8; nf++) {
                float bf[2];
                int va = (ks * 8 + cq) * VSTR + nf * 8 + g;
                bf[0] = Vc[va];
                bf[1] = Vc[va + 4 * VSTR];
                mma8(oacc[nf], a, bf);
            }
        }
        __syncthreads();
    }

    // Normalize, round (ctx feeds out-proj mma) and store
    float inv0 = 1.0f / lrow[0], inv8 = 1.0f / lrow[1];
    float* cb = ctx + (size_t)b * SLEN * DMODEL + h * HDIM;
    int row0 = q0 + rbase;
    #pragma unroll
    for (int nf = 0; nf < 8; nf++) {
        int col = nf * 8 + 2 * cq;
        float2 v0 = make_float2(tf32r(oacc[nf][0] * inv0), tf32r(oacc[nf][1] * inv0));
        float2 v1 = make_float2(tf32r(oacc[nf][2] * inv8), tf32r(oacc[nf][3] * inv8));
        *(float2*)&cb[(size_t)row0 * DMODEL + col] = v0;
        *(float2*)&cb[(size_t)(row0 + 8) * DMODEL + col] = v1;
    }
}

// ---------------------------------------------------------------------------
extern "C" void kernel_launch(void* const* d_in, const int* in_sizes, int n_in,
                              void* d_out, int out_size)
{
    const float* hs   = (const float*)d_in[0];
    const float* wqkv = (const float*)d_in[1];
    const float* wout = (const float*)d_in[2];
    float* out = (float*)d_out;

    float *qkv, *ctx, *wqkv_t, *wout_t;
    cudaGetSymbolAddress((void**)&qkv, g_qkv);
    cudaGetSymbolAddress((void**)&ctx, g_ctx);
    cudaGetSymbolAddress((void**)&wqkv_t, g_wqkv_t);
    cudaGetSymbolAddress((void**)&wout_t, g_wout_t);

    cudaFuncSetAttribute(attn_mma_kernel,
                         cudaFuncAttributeMaxDynamicSharedMemorySize, ATTN_SMEM_BYTES);
    cudaFuncSetAttribute(mma_gemm_kernel,
                         cudaFuncAttributeMaxDynamicSharedMemorySize, GEMM_SMEM_BYTES);

    // 0a) Transpose + round weights to [N, K] K-major tf32
    {
        dim3 blk(32, 8);
        transpose_kernel<<<dim3(QKV_LD / 32, DMODEL / 32), blk>>>(wqkv, wqkv_t, DMODEL, QKV_LD);
        transpose_kernel<<<dim3(DMODEL / 32, DMODEL / 32), blk>>>(wout, wout_t, DMODEL, DMODEL);
    }
    // 0b) Round hs into g_ctx (free until attention writes it)
    round_kernel<<<2048, 256>>>(hs, ctx, MROWS * DMODEL / 4);

    // 1) QKV projection (cp.async + mma tf32), rounded output
    {
        dim3 grid(QKV_LD / 128, MROWS / 128);
        mma_gemm_kernel<<<grid, 256, GEMM_SMEM_BYTES>>>(ctx, wqkv_t, qkv, MROWS, QKV_LD, DMODEL, 1);
    }

    // 2) Attention (mma tf32, cp.async double-buffered, 8 warps/CTA)
    {
        dim3 grid(SLEN / 128, NHEADS, BATCH);
        attn_mma_kernel<<<grid, 256, ATTN_SMEM_BYTES>>>(qkv, ctx);
    }

    // 3) Output projection (cp.async + mma tf32)
    {
        dim3 grid(DMODEL / 128, MROWS / 128);
        mma_gemm_kernel<<<grid, 256, GEMM_SMEM_BYTES>>>(ctx, wout_t, out, MROWS, DMODEL, DMODEL, 0);
    }
}

// round 15
// speedup vs baseline: 1.6678x; 1.0776x over previous
#include <cuda_runtime.h>
#include <cuda_bf16.h>
#include <cstdint>
#include <math.h>

// Problem constants
#define BATCH 4
#define SLEN 2048
#define DMODEL 1024
#define NHEADS 16
#define HDIM 64
#define QKV_LD 3072
#define MROWS (BATCH * SLEN)  // 8192

// Scratch (allocation-free rule: __device__ globals)
// g_ctx doubles as: rounded-hs (phase 1) then attention output (phase 2+).
__device__ float g_qkv[(size_t)MROWS * QKV_LD];       // [8192, 3072] (tf32-rounded)
__device__ float g_ctx[(size_t)MROWS * DMODEL];       // [8192, 1024]
__device__ float g_wqkv_t[(size_t)QKV_LD * DMODEL];   // [3072, 1024] (rounded)
__device__ float g_wout_t[(size_t)DMODEL * DMODEL];   // [1024, 1024] (rounded)

// ---------------------------------------------------------------------------
// Helpers
// ---------------------------------------------------------------------------
__device__ __forceinline__ float tf32r(float x) {
    uint32_t u;
    asm("cvt.rna.tf32.f32 %0, %1;" : "=r"(u) : "f"(x));
    return __uint_as_float(u);
}

// m16n8k8 tf32 MMA: C[16x8] += A[16x8] * B[8x8]
__device__ __forceinline__ void mma8(float* c, const float* a, const float* b) {
    const uint32_t* A = reinterpret_cast<const uint32_t*>(a);
    const uint32_t* B = reinterpret_cast<const uint32_t*>(b);
    asm volatile(
        "mma.sync.aligned.m16n8k8.row.col.f32.tf32.tf32.f32 "
        "{%0,%1,%2,%3}, {%4,%5,%6,%7}, {%8,%9}, {%0,%1,%2,%3};"
        : "+f"(c[0]), "+f"(c[1]), "+f"(c[2]), "+f"(c[3])
        : "r"(A[0]), "r"(A[1]), "r"(A[2]), "r"(A[3]), "r"(B[0]), "r"(B[1]));
}

// Fast exp on the FMA pipe. x <= ~1, result >= 0.
__device__ __forceinline__ float fexp(float x) {
    float t = fmaxf(x * 1.4426950408889634f, -120.0f);
    float r = t + 12582912.0f;
    int   i = __float_as_int(r) - 0x4B400000;
    float f = t - (r - 12582912.0f);
    float p = 0.0013333558f;
    p = fmaf(p, f, 0.0096181291f);
    p = fmaf(p, f, 0.0555041087f);
    p = fmaf(p, f, 0.2402265069f);
    p = fmaf(p, f, 0.6931471806f);
    p = fmaf(p, f, 1.0f);
    return __int_as_float(__float_as_int(p) + (i << 23));
}

#define CPA_COMMIT() asm volatile("cp.async.commit_group;" ::: "memory")
#define CPA(dst, src) \
    asm volatile("cp.async.cg.shared.global [%0], [%1], 16;" :: "r"(dst), "l"(src))

// ---------------------------------------------------------------------------
// Elementwise tf32 round: out[i] = tf32r(in[i]) (float4 grid-stride)
// ---------------------------------------------------------------------------
__global__ __launch_bounds__(256) void round_kernel(
    const float* __restrict__ in, float* __restrict__ out, int n4)
{
    int i = blockIdx.x * blockDim.x + threadIdx.x;
    int stride = gridDim.x * blockDim.x;
    for (; i < n4; i += stride) {
        float4 v = *(const float4*)&in[(size_t)i * 4];
        v.x = tf32r(v.x); v.y = tf32r(v.y); v.z = tf32r(v.z); v.w = tf32r(v.w);
        *(float4*)&out[(size_t)i * 4] = v;
    }
}

// ---------------------------------------------------------------------------
// Tiled transpose + tf32 round: out[c][r] = tf32r(in[r][c]), in is [R, C]
// ---------------------------------------------------------------------------
__global__ __launch_bounds__(256) void transpose_kernel(
    const float* __restrict__ in, float* __restrict__ out, int R, int C)
{
    __shared__ float t[32][33];
    int bx = blockIdx.x * 32, by = blockIdx.y * 32;
    int x = bx + threadIdx.x;
    #pragma unroll
    for (int i = 0; i < 32; i += 8) {
        int y = by + threadIdx.y + i;
        t[threadIdx.y + i][threadIdx.x] = in[(size_t)y * C + x];
    }
    __syncthreads();
    int xo = by + threadIdx.x;
    #pragma unroll
    for (int i = 0; i < 32; i += 8) {
        int yo = bx + threadIdx.y + i;
        out[(size_t)yo * R + xo] = tf32r(t[threadIdx.x][threadIdx.y + i]);
    }
}

// ---------------------------------------------------------------------------
// tf32 mma GEMM v3: C[M,N] = A[M,K] @ Bt[N,K]^T, inputs PRE-ROUNDED to tf32.
// CTA tile 128x128, BK=32, cp.async double-buffered.
// 4 warps in 2x2, warp tile 64x64 (LDS/mma = 1.0).
// GSTR=36: fragment banks = 4g+cq (perfect permutation, conflict-free).
// Dynamic smem (floats): As0 @0, As1 @4608, Bs0 @9216, Bs1 @13824 (73728 B)
// ---------------------------------------------------------------------------
#define GSTR 36
#define GEMM_SMEM_BYTES (18432 * 4)

__global__ __launch_bounds__(128) void mma_gemm_kernel(
    const float* __restrict__ A, const float* __restrict__ Bt,
    float* __restrict__ C, int M, int N, int K, int round_out)
{
    extern __shared__ float sm[];
    const int tid = threadIdx.x;
    const int lane = tid & 31, wid = tid >> 5;
    const int g = lane >> 2, cq = lane & 3;
    const int wm = (wid >> 1) * 64, wn = (wid & 1) * 64;

    const float* Ablk = A + (size_t)blockIdx.y * 128 * K;
    const float* Bblk = Bt + (size_t)blockIdx.x * 128 * K;

    uint32_t smbase;
    asm("{ .reg .u64 t; cvta.to.shared.u64 t, %1; cvt.u32.u64 %0, t; }" : "=r"(smbase) : "l"(sm));

    // 1024 float4 per matrix per chunk; 8 per thread each (128 threads)
    auto issue_chunk = [&](int k0, int buf) {
        uint32_t aoff = buf ? 4608u : 0u;
        uint32_t boff = buf ? 13824u : 9216u;
        #pragma unroll
        for (int i = 0; i < 8; i++) {
            int idx = tid + i * 128;           // 0..1023
            int row = idx >> 3;                // 0..127
            int c4 = (idx & 7) << 2;           // 0..28
            const float* asrc = &Ablk[(size_t)row * K + k0 + c4];
            CPA(smbase + (aoff + row * GSTR + c4) * 4, asrc);
            const float* bsrc = &Bblk[(size_t)row * K + k0 + c4];
            CPA(smbase + (boff + row * GSTR + c4) * 4, bsrc);
        }
        CPA_COMMIT();
    };

    issue_chunk(0, 0);

    float acc[4][8][4] = {};
    const int nchunks = K >> 5;

    for (int it = 0; it < nchunks; it++) {
        const int cur = it & 1;
        if (it + 1 < nchunks) {
            issue_chunk((it + 1) << 5, cur ^ 1);
            asm volatile("cp.async.wait_group 1;" ::: "memory");
        } else {
            asm volatile("cp.async.wait_group 0;" ::: "memory");
        }
        __syncthreads();

        const float* As = &sm[cur ? 4608 : 0];
        const float* Bs = &sm[cur ? 13824 : 9216];

        #pragma unroll
        for (int ks = 0; ks < 4; ks++) {
            float a[4][4], b[8][2];
            #pragma unroll
            for (int mi = 0; mi < 4; mi++) {
                int r = wm + mi * 16 + g;
                a[mi][0] = As[r * GSTR + ks * 8 + cq];
                a[mi][1] = As[(r + 8) * GSTR + ks * 8 + cq];
                a[mi][2] = As[r * GSTR + ks * 8 + cq + 4];
                a[mi][3] = As[(r + 8) * GSTR + ks * 8 + cq + 4];
            }
            #pragma unroll
            for (int nf = 0; nf < 8; nf++) {
                int n = wn + nf * 8 + g;
                b[nf][0] = Bs[n * GSTR + ks * 8 + cq];
                b[nf][1] = Bs[n * GSTR + ks * 8 + cq + 4];
            }
            #pragma unroll
            for (int mi = 0; mi < 4; mi++)
                #pragma unroll
                for (int nf = 0; nf < 8; nf++)
                    mma8(acc[mi][nf], a[mi], b[nf]);
        }
        __syncthreads();
    }

    #pragma unroll
    for (int mi = 0; mi < 4; mi++) {
        int row = blockIdx.y * 128 + wm + mi * 16 + g;
        #pragma unroll
        for (int nf = 0; nf < 8; nf++) {
            int col = blockIdx.x * 128 + wn + nf * 8 + 2 * cq;
            float4 vv = make_float4(acc[mi][nf][0], acc[mi][nf][1],
                                    acc[mi][nf][2], acc[mi][nf][3]);
            if (round_out) {
                vv.x = tf32r(vv.x); vv.y = tf32r(vv.y);
                vv.z = tf32r(vv.z); vv.w = tf32r(vv.w);
            }
            *(float2*)&C[(size_t)row * N + col] = make_float2(vv.x, vv.y);
            *(float2*)&C[(size_t)(row + 8) * N + col] = make_float2(vv.z, vv.w);
        }
    }
}

// ---------------------------------------------------------------------------
// Flash attention v5: CTA = (b, h, 128-query tile), 8 warps x 16 q-rows.
// Q fragments register-resident; K/V double-buffered via cp.async.
// Dynamic smem arena (floats):
//   K0 @ 0      (32x68 = 2176)     K1 @ 2176
//   V0 @ 4352   (32x72 = 2304)     V1 @ 6656
//   P  @ 8960   (per warp 16x36 = 576, 8 warps = 4608)
//   total 13568 floats = 54272 B.  Q staging [128x68=8704] aliases offset 0.
// ---------------------------------------------------------------------------
#define KSTR 68
#define VSTR 72
#define PSTR 36
#define SM_K0 0
#define SM_K1 2176
#define SM_V0 4352
#define SM_V1 6656
#define SM_P  8960
#define ATTN_SMEM_BYTES (13568 * 4)

__device__ __forceinline__ void issue_kv(uint32_t smbase, uint32_t kfoff, uint32_t vfoff,
                                         const float* kb, const float* vb, int kt, int tid)
{
    #pragma unroll
    for (int j = 0; j < 2; j++) {
        int idx = tid + j * 256;               // 0..511
        int row = idx >> 4;
        int c4 = (idx & 15) << 2;
        const float* ksrc = kb + (size_t)(kt + row) * QKV_LD + c4;
        CPA(smbase + (kfoff + row * KSTR + c4) * 4, ksrc);
        const float* vsrc = vb + (size_t)(kt + row) * QKV_LD + c4;
        CPA(smbase + (vfoff + row * VSTR + c4) * 4, vsrc);
    }
    CPA_COMMIT();
}

__global__ void __launch_bounds__(256) attn_mma_kernel(
    const float* __restrict__ qkv, float* __restrict__ ctx)
{
    extern __shared__ float sm[];
    const int qt = blockIdx.x, h = blockIdx.y, b = blockIdx.z;
    const int tid = threadIdx.x;
    const int lane = tid & 31, w = tid >> 5;
    const int g = lane >> 2, cq = lane & 3;

    const int q0 = qt * 128;
    const float* base = qkv + (size_t)b * SLEN * QKV_LD + h * HDIM;
    const float* kb = base + 1024;
    const float* vb = base + 2048;

    uint32_t smbase;
    asm("{ .reg .u64 t; cvta.to.shared.u64 t, %1; cvt.u32.u64 %0, t; }" : "=r"(smbase) : "l"(sm));

    // Phase 0: stage Q [128x64] (pre-rounded; scale by exact 0.125)
    for (int i = tid; i < 2048; i += 256) {
        int row = i >> 4;
        int c4 = (i & 15) << 2;
        float4 v = *(const float4*)&base[(size_t)(q0 + row) * QKV_LD + c4];
        v.x *= 0.125f; v.y *= 0.125f; v.z *= 0.125f; v.w *= 0.125f;
        *(float4*)&sm[row * KSTR + c4] = v;
    }
    __syncthreads();

    // Q fragments to registers: rows w*16+g, w*16+g+8
    float qreg[8][4];
    const int rbase = w * 16 + g;
    #pragma unroll
    for (int ks = 0; ks < 8; ks++) {
        int r0 = rbase * KSTR + ks * 8 + cq;
        int r8 = (rbase + 8) * KSTR + ks * 8 + cq;
        qreg[ks][0] = sm[r0];
        qreg[ks][1] = sm[r8];
        qreg[ks][2] = sm[r0 + 4];
        qreg[ks][3] = sm[r8 + 4];
    }
    __syncthreads();

    // Prologue: tile 0 into buffer 0
    issue_kv(smbase, SM_K0, SM_V0, kb, vb, 0, tid);

    float oacc[8][4] = {};
    float mrow[2] = {-1e30f, -1e30f};
    float lrow[2] = {0.0f, 0.0f};
    float* Pw = &sm[SM_P + w * (16 * PSTR)];

    for (int it = 0; it < SLEN / 32; it++) {
        const int cur = it & 1;
        if (it + 1 < SLEN / 32) {
            issue_kv(smbase, cur ? SM_K0 : SM_K1, cur ? SM_V0 : SM_V1,
                     kb, vb, (it + 1) * 32, tid);
            asm volatile("cp.async.wait_group 1;" ::: "memory");
        } else {
            asm volatile("cp.async.wait_group 0;" ::: "memory");
        }
        __syncthreads();

        const float* Kc = &sm[cur ? SM_K1 : SM_K0];
        const float* Vc = &sm[cur ? SM_V1 : SM_V0];

        // S = Q @ K^T : 16 rows x 32 keys per warp
        float s[4][4] = {};
        #pragma unroll
        for (int ks = 0; ks < 8; ks++) {
            #pragma unroll
            for (int nf = 0; nf < 4; nf++) {
                float bf[2];
                int kaddr = (nf * 8 + g) * KSTR + ks * 8 + cq;
                bf[0] = Kc[kaddr];
                bf[1] = Kc[kaddr + 4];
                mma8(s[nf], qreg[ks], bf);
            }
        }

        // Online softmax
        float rmax0 = -1e30f, rmax8 = -1e30f;
        #pragma unroll
        for (int nf = 0; nf < 4; nf++) {
            rmax0 = fmaxf(rmax0, fmaxf(s[nf][0], s[nf][1]));
            rmax8 = fmaxf(rmax8, fmaxf(s[nf][2], s[nf][3]));
        }
        rmax0 = fmaxf(rmax0, __shfl_xor_sync(0xffffffffu, rmax0, 1));
        rmax0 = fmaxf(rmax0, __shfl_xor_sync(0xffffffffu, rmax0, 2));
        rmax8 = fmaxf(rmax8, __shfl_xor_sync(0xffffffffu, rmax8, 1));
        rmax8 = fmaxf(rmax8, __shfl_xor_sync(0xffffffffu, rmax8, 2));

        float mn0 = fmaxf(mrow[0], rmax0), mn8 = fmaxf(mrow[1], rmax8);
        float corr0 = fexp(mrow[0] - mn0), corr8 = fexp(mrow[1] - mn8);
        mrow[0] = mn0; mrow[1] = mn8;

        float sum0 = 0.0f, sum8 = 0.0f;
        #pragma unroll
        for (int nf = 0; nf < 4; nf++) {
            float p0 = fexp(s[nf][0] - mn0);
            float p1 = fexp(s[nf][1] - mn0);
            float p2 = fexp(s[nf][2] - mn8);
            float p3 = fexp(s[nf][3] - mn8);
            sum0 += p0 + p1;
            sum8 += p2 + p3;
            *(float2*)&Pw[g * PSTR + nf * 8 + 2 * cq] = make_float2(tf32r(p0), tf32r(p1));
            *(float2*)&Pw[(g + 8) * PSTR + nf * 8 + 2 * cq] = make_float2(tf32r(p2), tf32r(p3));
        }
        sum0 += __shfl_xor_sync(0xffffffffu, sum0, 1);
        sum0 += __shfl_xor_sync(0xffffffffu, sum0, 2);
        sum8 += __shfl_xor_sync(0xffffffffu, sum8, 1);
        sum8 += __shfl_xor_sync(0xffffffffu, sum8, 2);
        lrow[0] = lrow[0] * corr0 + sum0;
        lrow[1] = lrow[1] * corr8 + sum8;

        #pragma unroll
        for (int nf = 0; nf < 8; nf++) {
            oacc[nf][0] *= corr0; oacc[nf][1] *= corr0;
            oacc[nf][2] *= corr8; oacc[nf][3] *= corr8;
        }
        __syncwarp();

        // O += P @ V : 16 rows x 64 dims per warp
        #pragma unroll
        for (int ks = 0; ks < 4; ks++) {
            float a[4];
            int p0a = g * PSTR + ks * 8 + cq;
            int p8a = (g + 8) * PSTR + ks * 8 + cq;
            a[0] = Pw[p0a];
            a[1] = Pw[p8a];
            a[2] = Pw[p0a + 4];
            a[3] = Pw[p8a + 4];
            #pragma unroll
            for (int nf = 0; nf < 8; nf++) {
                float bf[2];
                int va = (ks * 8 + cq) * VSTR + nf * 8 + g;
                bf[0] = Vc[va];
                bf[1] = Vc[va + 4 * VSTR];
                mma8(oacc[nf], a, bf);
            }
        }
        __syncthreads();
    }

    // Normalize, round (ctx feeds out-proj mma) and store
    float inv0 = 1.0f / lrow[0], inv8 = 1.0f / lrow[1];
    float* cb = ctx + (size_t)b * SLEN * DMODEL + h * HDIM;
    int row0 = q0 + rbase;
    #pragma unroll
    for (int nf = 0; nf < 8; nf++) {
        int col = nf * 8 + 2 * cq;
        float2 v0 = make_float2(tf32r(oacc[nf][0] * inv0), tf32r(oacc[nf][1] * inv0));
        float2 v1 = make_float2(tf32r(oacc[nf][2] * inv8), tf32r(oacc[nf][3] * inv8));
        *(float2*)&cb[(size_t)row0 * DMODEL + col] = v0;
        *(float2*)&cb[(size_t)(row0 + 8) * DMODEL + col] = v1;
    }
}

// ---------------------------------------------------------------------------
extern "C" void kernel_launch(void* const* d_in, const int* in_sizes, int n_in,
                              void* d_out, int out_size)
{
    const float* hs   = (const float*)d_in[0];
    const float* wqkv = (const float*)d_in[1];
    const float* wout = (const float*)d_in[2];
    float* out = (float*)d_out;

    float *qkv, *ctx, *wqkv_t, *wout_t;
    cudaGetSymbolAddress((void**)&qkv, g_qkv);
    cudaGetSymbolAddress((void**)&ctx, g_ctx);
    cudaGetSymbolAddress((void**)&wqkv_t, g_wqkv_t);
    cudaGetSymbolAddress((void**)&wout_t, g_wout_t);

    cudaFuncSetAttribute(attn_mma_kernel,
                         cudaFuncAttributeMaxDynamicSharedMemorySize, ATTN_SMEM_BYTES);
    cudaFuncSetAttribute(mma_gemm_kernel,
                         cudaFuncAttributeMaxDynamicSharedMemorySize, GEMM_SMEM_BYTES);

    // 0a) Transpose + round weights to [N, K] K-major tf32
    {
        dim3 blk(32, 8);
        transpose_kernel<<<dim3(QKV_LD / 32, DMODEL / 32), blk>>>(wqkv, wqkv_t, DMODEL, QKV_LD);
        transpose_kernel<<<dim3(DMODEL / 32, DMODEL / 32), blk>>>(wout, wout_t, DMODEL, DMODEL);
    }
    // 0b) Round hs into g_ctx (free until attention writes it)
    round_kernel<<<2048, 256>>>(hs, ctx, MROWS * DMODEL / 4);

    // 1) QKV projection (cp.async + mma tf32, 64x64 warp tile), rounded output
    {
        dim3 grid(QKV_LD / 128, MROWS / 128);
        mma_gemm_kernel<<<grid, 128, GEMM_SMEM_BYTES>>>(ctx, wqkv_t, qkv, MROWS, QKV_LD, DMODEL, 1);
    }

    // 2) Attention (mma tf32, cp.async double-buffered, 8 warps/CTA)
    {
        dim3 grid(SLEN / 128, NHEADS, BATCH);
        attn_mma_kernel<<<grid, 256, ATTN_SMEM_BYTES>>>(qkv, ctx);
    }

    // 3) Output projection (cp.async + mma tf32, 64x64 warp tile)
    {
        dim3 grid(DMODEL / 128, MROWS / 128);
        mma_gemm_kernel<<<grid, 128, GEMM_SMEM_BYTES>>>(ctx, wout_t, out, MROWS, DMODEL, DMODEL, 0);
    }
}